// round 7
// baseline (speedup 1.0000x reference)
#include <cuda_runtime.h>
#include <math.h>

// LSTM: S=512, B=64, I=H=1024, fp32.
//  Phase 1: gates_x = x @ W_ih^T + b_ih + b_hh   (one GEMM, FFMA2)
//  Phase 2: ONE persistent kernel runs all 512 recurrent steps.
//    - 128 CTAs x 256 threads, all co-resident (1 CTA/SM, 128 <= 148 SMs)
//    - W_hh tile (32 rows) resident in SMEM for the entire run
//    - cell state c resident in registers for the entire run
//    - global release/acquire spin barrier between steps (monotonic counter,
//      reset by an init kernel at the start of every launch)
//
// Output layout: [0,S*B*H) output; then h_last [B*H]; then c_last [B*H].

typedef unsigned long long u64;

#define SEQ 512
#define BATCH 64
#define HID 1024
#define G4 4096
#define BH (BATCH * HID)
#define NCTA 128

// scratch (allocation-free rule: __device__ globals)
__device__ float g_gx[(size_t)SEQ * BATCH * G4];   // precomputed input gates
__device__ unsigned int g_bar;                     // grid barrier counter

static __device__ __forceinline__ void ffma2(u64 &d, u64 a, u64 b) {
    asm volatile("fma.rn.f32x2 %0, %1, %2, %0;" : "+l"(d) : "l"(a), "l"(b));
}
static __device__ __forceinline__ u64 pack2(float x, float y) {
    u64 r; asm("mov.b64 %0, {%1, %2};" : "=l"(r) : "f"(x), "f"(y)); return r;
}
static __device__ __forceinline__ float hadd2(u64 v) {
    float x, y; asm("mov.b64 {%0, %1}, %2;" : "=f"(x), "=f"(y) : "l"(v));
    return x + y;
}

__global__ void init_bar() { g_bar = 0u; }

// ---------------------------------------------------------------------------
// Phase 1 GEMM: C[m][n] = sum_k X[m][k] * Wih[n][k] + (bih[n] + bhh[n])
// M=32768, N=4096, K=1024. BM=BN=128, BK=16, 512 threads, 8m x 4n per thread.
// ---------------------------------------------------------------------------
__global__ __launch_bounds__(512, 1)
void gemm_gates_x(const float* __restrict__ X, const float* __restrict__ W,
                  const float* __restrict__ bih, const float* __restrict__ bhh)
{
    __shared__ u64 As[2][8][129];
    __shared__ u64 Bs[2][8][129];

    const int t  = threadIdx.x;
    const int n0 = blockIdx.x * 128;
    const int m0 = blockIdx.y * 128;

    const int lrow = t >> 2;
    const int lq   = t & 3;
    const float* ap = X + (size_t)(m0 + lrow) * 1024 + lq * 4;
    const float* bp = W + (size_t)(n0 + lrow) * 1024 + lq * 4;

    const int tn = t & 31;
    const int tm = t >> 5;

    u64 acc[8][4];
#pragma unroll
    for (int i = 0; i < 8; i++)
#pragma unroll
        for (int jj = 0; jj < 4; jj++) acc[i][jj] = 0ull;

    float4 av = *(const float4*)ap;
    float4 bv = *(const float4*)bp;
    As[0][lq * 2][lrow]     = pack2(av.x, av.y);
    As[0][lq * 2 + 1][lrow] = pack2(av.z, av.w);
    Bs[0][lq * 2][lrow]     = pack2(bv.x, bv.y);
    Bs[0][lq * 2 + 1][lrow] = pack2(bv.z, bv.w);
    __syncthreads();

    int buf = 0;
    for (int kt = 0; kt < 64; kt++) {
        if (kt < 63) {
            av = *(const float4*)(ap + (kt + 1) * 16);
            bv = *(const float4*)(bp + (kt + 1) * 16);
        }
#pragma unroll
        for (int q = 0; q < 8; q++) {
            u64 a8[8], b4[4];
#pragma unroll
            for (int i = 0; i < 8; i++) a8[i] = As[buf][q][tm * 8 + i];
#pragma unroll
            for (int jj = 0; jj < 4; jj++) b4[jj] = Bs[buf][q][tn + 32 * jj];
#pragma unroll
            for (int i = 0; i < 8; i++)
#pragma unroll
                for (int jj = 0; jj < 4; jj++) ffma2(acc[i][jj], a8[i], b4[jj]);
        }
        if (kt < 63) {
            As[buf ^ 1][lq * 2][lrow]     = pack2(av.x, av.y);
            As[buf ^ 1][lq * 2 + 1][lrow] = pack2(av.z, av.w);
            Bs[buf ^ 1][lq * 2][lrow]     = pack2(bv.x, bv.y);
            Bs[buf ^ 1][lq * 2 + 1][lrow] = pack2(bv.z, bv.w);
            __syncthreads();
            buf ^= 1;
        }
    }

#pragma unroll
    for (int jj = 0; jj < 4; jj++) {
        const int n = n0 + tn + 32 * jj;
        const float bias = bih[n] + bhh[n];
#pragma unroll
        for (int i = 0; i < 8; i++) {
            const int m = m0 + tm * 8 + i;
            g_gx[(size_t)m * G4 + n] = hadd2(acc[i][jj]) + bias;
        }
    }
}

// ---------------------------------------------------------------------------
// Phase 2: persistent recurrent kernel.
// 128 CTAs x 256 threads. CTA owns j0..j0+7 hidden cols (x 4 gates = 32 W rows,
// kept in SMEM for all 512 steps). Thread: j = tid&7, 2 batches, 4 gates ->
// 8 packed f32x2 accumulators + 2 register-resident cell states.
// Per step: 4 h-chunks of 256 k staged to SMEM, GEMV, fused cell update,
// h written to out[t], release/acquire grid barrier.
//
// SMEM: ws[32][513] u64 (131,328 B) + hs[64][129] u64 (66,048 B) = 197,376 B.
// Row pads (513/129 u64) make both LDS.64 patterns bank-conflict-free.
// ---------------------------------------------------------------------------
#define WS_U64 (32 * 513)
#define STEP_SMEM ((WS_U64 + 64 * 129) * 8)

__global__ __launch_bounds__(256, 1)
void lstm_persist(const float* __restrict__ h0, const float* __restrict__ c0,
                  const float* __restrict__ Whh, float* __restrict__ out)
{
    extern __shared__ u64 sm[];
    u64 (*ws)[513] = (u64(*)[513])sm;            // [32 W rows][512 kpair + pad]
    u64 (*hs)[129] = (u64(*)[129])(sm + WS_U64); // [64 b][128 kpair + pad]

    const int tid = threadIdx.x;
    const int j   = tid & 7;
    const int bq  = tid >> 3;        // 0..31
    const int b0  = bq * 2;
    const int j0  = blockIdx.x * 8;
    const int col = j0 + j;

    // ---- load this CTA's 32 W_hh rows into SMEM once ----
    for (int idx = tid; idx < 8192; idx += 256) {       // 8192 float4
        const int r  = idx >> 8;                        // 0..31
        const int c4 = idx & 255;                       // 0..255
        const int grow = (r >> 3) * 1024 + j0 + (r & 7);
        float4 v = *(const float4*)(Whh + (size_t)grow * 1024 + c4 * 4);
        ws[r][c4 * 2]     = pack2(v.x, v.y);
        ws[r][c4 * 2 + 1] = pack2(v.z, v.w);
    }

    // ---- cell state lives in registers for the whole run ----
    float creg[2];
    creg[0] = c0[(b0 + 0) * HID + col];
    creg[1] = c0[(b0 + 1) * HID + col];
    __syncthreads();

    for (int t = 0; t < SEQ; t++) {
        // prefetch this step's input-gate values (DRAM latency hidden by GEMV)
        float gx[2][4];
#pragma unroll
        for (int bi = 0; bi < 2; bi++)
#pragma unroll
            for (int g = 0; g < 4; g++)
                gx[bi][g] = g_gx[((size_t)t * BATCH + b0 + bi) * G4 + g * 1024 + col];

        // acquire: wait until all CTAs finished step t-1 (h[t-1] visible)
        if (t > 0) {
            if (tid == 0) {
                const unsigned target = (unsigned)(NCTA * t);
                while (atomicAdd(&g_bar, 0u) < target) { }
                __threadfence();
            }
            __syncthreads();
        }

        const float* h_in = (t == 0) ? h0 : (out + (size_t)(t - 1) * BH);

        u64 acc[4][2];
#pragma unroll
        for (int g = 0; g < 4; g++) { acc[g][0] = 0ull; acc[g][1] = 0ull; }

        for (int ck = 0; ck < 4; ck++) {
            const int kbase = ck * 256;
            // stage h chunk: 64 rows x 256 floats (coalesced float4)
            for (int idx = tid; idx < 4096; idx += 256) {
                const int r = idx >> 6, c4 = idx & 63;
                float4 v = *(const float4*)(h_in + r * 1024 + kbase + c4 * 4);
                hs[r][c4 * 2]     = pack2(v.x, v.y);
                hs[r][c4 * 2 + 1] = pack2(v.z, v.w);
            }
            __syncthreads();

            const int gk0 = ck * 128;
#pragma unroll 8
            for (int kp = 0; kp < 128; kp++) {
                u64 w2[4], h2[2];
#pragma unroll
                for (int g = 0; g < 4; g++) w2[g] = ws[g * 8 + j][gk0 + kp];
                h2[0] = hs[b0][kp];
                h2[1] = hs[b0 + 1][kp];
#pragma unroll
                for (int g = 0; g < 4; g++) {
                    ffma2(acc[g][0], w2[g], h2[0]);
                    ffma2(acc[g][1], w2[g], h2[1]);
                }
            }
            __syncthreads();
        }

        // fused cell update (c in registers, h -> global)
#pragma unroll
        for (int bi = 0; bi < 2; bi++) {
            const int b = b0 + bi;
            const float gi = hadd2(acc[0][bi]) + gx[bi][0];
            const float gf = hadd2(acc[1][bi]) + gx[bi][1];
            const float gg = hadd2(acc[2][bi]) + gx[bi][2];
            const float go = hadd2(acc[3][bi]) + gx[bi][3];

            const float ig = 1.0f / (1.0f + expf(-gi));
            const float fg = 1.0f / (1.0f + expf(-gf));
            const float gt = tanhf(gg);
            const float og = 1.0f / (1.0f + expf(-go));

            const float cn = fg * creg[bi] + ig * gt;
            const float hn = og * tanhf(cn);
            creg[bi] = cn;

            out[(size_t)t * BH + b * HID + col] = hn;
            if (t == SEQ - 1) {
                out[(size_t)SEQ * BH + b * HID + col] = hn;        // h_last
                out[(size_t)SEQ * BH + BH + b * HID + col] = cn;   // c_last
            }
        }

        // release: publish h[t]
        if (t < SEQ - 1) {
            __syncthreads();
            if (tid == 0) {
                __threadfence();
                atomicAdd(&g_bar, 1u);
            }
        }
    }
}

extern "C" void kernel_launch(void* const* d_in, const int* in_sizes, int n_in,
                              void* d_out, int out_size)
{
    const float* x    = (const float*)d_in[0];
    const float* h0   = (const float*)d_in[1];
    const float* c0   = (const float*)d_in[2];
    const float* Wih  = (const float*)d_in[3];
    const float* bih  = (const float*)d_in[4];
    const float* Whh  = (const float*)d_in[5];
    const float* bhh  = (const float*)d_in[6];
    float* out = (float*)d_out;

    static int configured = 0;
    if (!configured) {
        cudaFuncSetAttribute(lstm_persist,
                             cudaFuncAttributeMaxDynamicSharedMemorySize,
                             STEP_SMEM);
        configured = 1;
    }

    init_bar<<<1, 1>>>();
    gemm_gates_x<<<dim3(32, 256), 512>>>(x, Wih, bih, bhh);
    lstm_persist<<<NCTA, 256, STEP_SMEM>>>(h0, c0, Whh, out);
}

// round 8
// speedup vs baseline: 1.5243x; 1.5243x over previous
#include <cuda_runtime.h>
#include <math.h>

// LSTM: S=512, B=64, I=H=1024, fp32.
//  Phase 1: gates_x = x @ W_ih^T + b_ih + b_hh   (one GEMM, packed FFMA2)
//  Phase 2: ONE persistent kernel runs all 512 recurrent steps.
//    - 128 CTAs x 256 threads, all co-resident (1 CTA/SM, 128 <= 148 SMs)
//    - W_hh tile (32 rows) resident in SMEM for the entire run
//    - cell state c resident in registers for the entire run
//    - DISTRIBUTED flag grid barrier: per-CTA slot, volatile store release,
//      per-thread distinct-slot volatile-load polling with nanosleep backoff.
//      (R5's single-counter atomicAdd spin serialized on one L2 address and
//      cost ~17us/step; this removes all atomic-ALU traffic from the wait.)
//
// Output layout: [0,S*B*H) output; then h_last [B*H]; then c_last [B*H].

typedef unsigned long long u64;

#define SEQ 512
#define BATCH 64
#define HID 1024
#define G4 4096
#define BH (BATCH * HID)
#define NCTA 128

// scratch (allocation-free rule: __device__ globals)
__device__ float g_gx[(size_t)SEQ * BATCH * G4];        // precomputed input gates
__device__ volatile unsigned int g_arrive[NCTA];        // per-CTA step flags

static __device__ __forceinline__ void ffma2(u64 &d, u64 a, u64 b) {
    asm volatile("fma.rn.f32x2 %0, %1, %2, %0;" : "+l"(d) : "l"(a), "l"(b));
}
static __device__ __forceinline__ u64 pack2(float x, float y) {
    u64 r; asm("mov.b64 %0, {%1, %2};" : "=l"(r) : "f"(x), "f"(y)); return r;
}
static __device__ __forceinline__ float hadd2(u64 v) {
    float x, y; asm("mov.b64 {%0, %1}, %2;" : "=f"(x), "=f"(y) : "l"(v));
    return x + y;
}

__global__ void init_bar() {
    if (threadIdx.x < NCTA) g_arrive[threadIdx.x] = 0u;
}

// ---------------------------------------------------------------------------
// Phase 1 GEMM: C[m][n] = sum_k X[m][k] * Wih[n][k] + (bih[n] + bhh[n])
// M=32768, N=4096, K=1024. BM=BN=128, BK=16, 512 threads, 8m x 4n per thread.
// ---------------------------------------------------------------------------
__global__ __launch_bounds__(512, 1)
void gemm_gates_x(const float* __restrict__ X, const float* __restrict__ W,
                  const float* __restrict__ bih, const float* __restrict__ bhh)
{
    __shared__ u64 As[2][8][129];
    __shared__ u64 Bs[2][8][129];

    const int t  = threadIdx.x;
    const int n0 = blockIdx.x * 128;
    const int m0 = blockIdx.y * 128;

    const int lrow = t >> 2;
    const int lq   = t & 3;
    const float* ap = X + (size_t)(m0 + lrow) * 1024 + lq * 4;
    const float* bp = W + (size_t)(n0 + lrow) * 1024 + lq * 4;

    const int tn = t & 31;
    const int tm = t >> 5;

    u64 acc[8][4];
#pragma unroll
    for (int i = 0; i < 8; i++)
#pragma unroll
        for (int jj = 0; jj < 4; jj++) acc[i][jj] = 0ull;

    float4 av = *(const float4*)ap;
    float4 bv = *(const float4*)bp;
    As[0][lq * 2][lrow]     = pack2(av.x, av.y);
    As[0][lq * 2 + 1][lrow] = pack2(av.z, av.w);
    Bs[0][lq * 2][lrow]     = pack2(bv.x, bv.y);
    Bs[0][lq * 2 + 1][lrow] = pack2(bv.z, bv.w);
    __syncthreads();

    int buf = 0;
    for (int kt = 0; kt < 64; kt++) {
        if (kt < 63) {
            av = *(const float4*)(ap + (kt + 1) * 16);
            bv = *(const float4*)(bp + (kt + 1) * 16);
        }
#pragma unroll
        for (int q = 0; q < 8; q++) {
            u64 a8[8], b4[4];
#pragma unroll
            for (int i = 0; i < 8; i++) a8[i] = As[buf][q][tm * 8 + i];
#pragma unroll
            for (int jj = 0; jj < 4; jj++) b4[jj] = Bs[buf][q][tn + 32 * jj];
#pragma unroll
            for (int i = 0; i < 8; i++)
#pragma unroll
                for (int jj = 0; jj < 4; jj++) ffma2(acc[i][jj], a8[i], b4[jj]);
        }
        if (kt < 63) {
            As[buf ^ 1][lq * 2][lrow]     = pack2(av.x, av.y);
            As[buf ^ 1][lq * 2 + 1][lrow] = pack2(av.z, av.w);
            Bs[buf ^ 1][lq * 2][lrow]     = pack2(bv.x, bv.y);
            Bs[buf ^ 1][lq * 2 + 1][lrow] = pack2(bv.z, bv.w);
            __syncthreads();
            buf ^= 1;
        }
    }

#pragma unroll
    for (int jj = 0; jj < 4; jj++) {
        const int n = n0 + tn + 32 * jj;
        const float bias = bih[n] + bhh[n];
#pragma unroll
        for (int i = 0; i < 8; i++) {
            const int m = m0 + tm * 8 + i;
            g_gx[(size_t)m * G4 + n] = hadd2(acc[i][jj]) + bias;
        }
    }
}

// ---------------------------------------------------------------------------
// Phase 2: persistent recurrent kernel.
// 128 CTAs x 256 threads. CTA owns 8 hidden cols (x4 gates = 32 W_hh rows in
// SMEM for all 512 steps). Thread: j = tid&7, 2 batches -> 8 packed f32x2
// accumulators, 2 register-resident cell states.
// SMEM: ws[32][513] u64 (131,328 B) + hs[64][129] u64 (66,048 B) = 197,376 B.
// ---------------------------------------------------------------------------
#define WS_U64 (32 * 513)
#define STEP_SMEM ((WS_U64 + 64 * 129) * 8)

__global__ __launch_bounds__(256, 1)
void lstm_persist(const float* __restrict__ h0, const float* __restrict__ c0,
                  const float* __restrict__ Whh, float* __restrict__ out)
{
    extern __shared__ u64 sm[];
    u64 (*ws)[513] = (u64(*)[513])sm;            // [32 W rows][512 kpair + pad]
    u64 (*hs)[129] = (u64(*)[129])(sm + WS_U64); // [64 b][128 kpair + pad]

    const int tid = threadIdx.x;
    const int j   = tid & 7;
    const int bq  = tid >> 3;        // 0..31
    const int b0  = bq * 2;
    const int j0  = blockIdx.x * 8;
    const int col = j0 + j;

    // ---- load this CTA's 32 W_hh rows into SMEM once ----
    for (int idx = tid; idx < 8192; idx += 256) {       // 8192 float4
        const int r  = idx >> 8;
        const int c4 = idx & 255;
        const int grow = (r >> 3) * 1024 + j0 + (r & 7);
        float4 v = *(const float4*)(Whh + (size_t)grow * 1024 + c4 * 4);
        ws[r][c4 * 2]     = pack2(v.x, v.y);
        ws[r][c4 * 2 + 1] = pack2(v.z, v.w);
    }

    // ---- cell state lives in registers for the whole run ----
    float creg[2];
    creg[0] = c0[(b0 + 0) * HID + col];
    creg[1] = c0[(b0 + 1) * HID + col];
    __syncthreads();

    for (int t = 0; t < SEQ; t++) {
        // prefetch this step's input-gate values (static data, no ordering dep)
        float gx[2][4];
#pragma unroll
        for (int bi = 0; bi < 2; bi++)
#pragma unroll
            for (int g = 0; g < 4; g++)
                gx[bi][g] = g_gx[((size_t)t * BATCH + b0 + bi) * G4 + g * 1024 + col];

        // acquire: every thread tid<NCTA polls ONE distinct CTA's flag.
        // Plain L2 loads (volatile), distinct addresses, nanosleep backoff:
        // no atomic-ALU serialization, near-zero standing traffic.
        if (t > 0) {
            if (tid < NCTA) {
                while (g_arrive[tid] < (unsigned)t) { __nanosleep(20); }
            }
            __threadfence();
            __syncthreads();
        }

        const float* h_in = (t == 0) ? h0 : (out + (size_t)(t - 1) * BH);

        u64 acc[4][2];
#pragma unroll
        for (int g = 0; g < 4; g++) { acc[g][0] = 0ull; acc[g][1] = 0ull; }

        for (int ck = 0; ck < 4; ck++) {
            const int kbase = ck * 256;
            // stage h chunk: 64 rows x 256 floats; __ldcg = L2-coherent path
            for (int idx = tid; idx < 4096; idx += 256) {
                const int r = idx >> 6, c4 = idx & 63;
                float4 v = __ldcg((const float4*)(h_in + r * 1024 + kbase + c4 * 4));
                hs[r][c4 * 2]     = pack2(v.x, v.y);
                hs[r][c4 * 2 + 1] = pack2(v.z, v.w);
            }
            __syncthreads();

            const int gk0 = ck * 128;
#pragma unroll 8
            for (int kp = 0; kp < 128; kp++) {
                u64 w2[4], h2[2];
#pragma unroll
                for (int g = 0; g < 4; g++) w2[g] = ws[g * 8 + j][gk0 + kp];
                h2[0] = hs[b0][kp];
                h2[1] = hs[b0 + 1][kp];
#pragma unroll
                for (int g = 0; g < 4; g++) {
                    ffma2(acc[g][0], w2[g], h2[0]);
                    ffma2(acc[g][1], w2[g], h2[1]);
                }
            }
            __syncthreads();
        }

        // fused cell update (c in registers, h -> global)
#pragma unroll
        for (int bi = 0; bi < 2; bi++) {
            const int b = b0 + bi;
            const float gi = hadd2(acc[0][bi]) + gx[bi][0];
            const float gf = hadd2(acc[1][bi]) + gx[bi][1];
            const float gg = hadd2(acc[2][bi]) + gx[bi][2];
            const float go = hadd2(acc[3][bi]) + gx[bi][3];

            const float ig = 1.0f / (1.0f + expf(-gi));
            const float fg = 1.0f / (1.0f + expf(-gf));
            const float gt = tanhf(gg);
            const float og = 1.0f / (1.0f + expf(-go));

            const float cn = fg * creg[bi] + ig * gt;
            const float hn = og * tanhf(cn);
            creg[bi] = cn;

            out[(size_t)t * BH + b * HID + col] = hn;
            if (t == SEQ - 1) {
                out[(size_t)SEQ * BH + b * HID + col] = hn;        // h_last
                out[(size_t)SEQ * BH + BH + b * HID + col] = cn;   // c_last
            }
        }

        // release: publish h[t] via this CTA's own flag slot
        if (t < SEQ - 1) {
            __syncthreads();
            if (tid == 0) {
                __threadfence();
                g_arrive[blockIdx.x] = (unsigned)(t + 1);
            }
        }
    }
}

extern "C" void kernel_launch(void* const* d_in, const int* in_sizes, int n_in,
                              void* d_out, int out_size)
{
    const float* x    = (const float*)d_in[0];
    const float* h0   = (const float*)d_in[1];
    const float* c0   = (const float*)d_in[2];
    const float* Wih  = (const float*)d_in[3];
    const float* bih  = (const float*)d_in[4];
    const float* Whh  = (const float*)d_in[5];
    const float* bhh  = (const float*)d_in[6];
    float* out = (float*)d_out;

    cudaFuncSetAttribute(lstm_persist,
                         cudaFuncAttributeMaxDynamicSharedMemorySize, STEP_SMEM);

    init_bar<<<1, NCTA>>>();
    gemm_gates_x<<<dim3(32, 256), 512>>>(x, Wih, bih, bhh);
    lstm_persist<<<NCTA, 256, STEP_SMEM>>>(h0, c0, Whh, out);
}